// round 2
// baseline (speedup 1.0000x reference)
#include <cuda_runtime.h>
#include <float.h>
#include <math.h>

#define NPTS 4096
#define NB 2
#define NN 8192
#define DD 64
#define KK 5
#define NKB (NPTS*KK)      /* 20480 flat (k-major) per batch */
#define EDGES (NB*NKB)     /* 40960 edges */
#define SPLITS 8
#define PRANGE (NPTS/SPLITS)   /* 512 points per block */
#define PT 128                 /* point tile */
#define QT 32                  /* queries per block */

/* ---------------- scratch (device globals; no allocation allowed) -------- */
__device__ float    g_xf1[NN*DD];
__device__ float    g_ge1[NN*DD];
__device__ float    g_ge2[NN*DD];
__device__ float    g_sq [NN];
__device__ int      g_idx1[NB*NKB];
__device__ int      g_idx2[NB*NKB];
__device__ float    g_A  [NN*DD];
__device__ float    g_B  [NN*DD];
__device__ unsigned g_acc[NN*DD];
__device__ float    g_x2 [NN*DD];
__device__ float    g_x3 [NN*DD];
__device__ float    g_Wdiff[DD*DD];
__device__ float    g_pv [NB*NPTS*SPLITS*5];
__device__ int      g_pi [NB*NPTS*SPLITS*5];

/* ordered float<->uint key (monotone map, finite floats) */
__device__ __forceinline__ unsigned fkey(float f) {
    unsigned u = __float_as_uint(f);
    return u ^ ((unsigned)(((int)u) >> 31) | 0x80000000u);
}
__device__ __forceinline__ float fdec(unsigned u) {
    unsigned v = u ^ ((u & 0x80000000u) ? 0x80000000u : 0xFFFFFFFFu);
    return __uint_as_float(v);
}
#define NEG_MAX_KEY 0x00800000u   /* fkey(-FLT_MAX) */

/* cp.async helpers */
__device__ __forceinline__ void cp_async16(void* smem_dst, const void* gsrc) {
    unsigned s = (unsigned)__cvta_generic_to_shared(smem_dst);
    asm volatile("cp.async.ca.shared.global [%0], [%1], 16;" :: "r"(s), "l"(gsrc));
}
__device__ __forceinline__ void cp_commit() {
    asm volatile("cp.async.commit_group;" ::: "memory");
}
template<int N> __device__ __forceinline__ void cp_wait() {
    asm volatile("cp.async.wait_group %0;" :: "n"(N) : "memory");
}

/* ---------------- generic small GEMM: Y = act(X@W + b), 64 rows/block ---- */
template<int NCOL>
__global__ __launch_bounds__(256) void gemm_act(
    const float* __restrict__ X1, int k1,
    const float* __restrict__ X2, int k2,
    const float* __restrict__ W, const float* __restrict__ bias,
    float* __restrict__ Y, int act)
{
    constexpr int G  = NCOL / 4;
    constexpr int TY = 256 / G;
    constexpr int R  = 64 / TY;
    __shared__ float Ws[128 * NCOL];
    __shared__ float Xs[64 * 33];
    __shared__ float bs[NCOL];
    const int t = threadIdx.x;
    const int rowBase = blockIdx.x * 64;
    const int KD = k1 + k2;

    for (int f = t; f < KD * NCOL; f += 256) Ws[f] = W[f];
    if (t < NCOL) bs[t] = (bias != nullptr) ? bias[t] : 0.0f;

    const int tx = t % G, ty = t / G;
    float acc[R][4];
#pragma unroll
    for (int rr = 0; rr < R; rr++) { acc[rr][0]=0.f; acc[rr][1]=0.f; acc[rr][2]=0.f; acc[rr][3]=0.f; }

    for (int ko = 0; ko < KD; ko += 32) {
        const float* Xsrc; int stride, koff;
        if (ko < k1) { Xsrc = X1; stride = k1; koff = ko; }
        else         { Xsrc = X2; stride = k2; koff = ko - k1; }
        __syncthreads();
        for (int f = t; f < 64 * 32; f += 256) {
            int r = f >> 5, k = f & 31;
            Xs[r * 33 + k] = Xsrc[(rowBase + r) * stride + koff + k];
        }
        __syncthreads();
#pragma unroll
        for (int k = 0; k < 32; k++) {
            float4 w4 = *(const float4*)(Ws + (ko + k) * NCOL + tx * 4);
#pragma unroll
            for (int rr = 0; rr < R; rr++) {
                float xv = Xs[(ty + rr * TY) * 33 + k];
                acc[rr][0] += xv * w4.x; acc[rr][1] += xv * w4.y;
                acc[rr][2] += xv * w4.z; acc[rr][3] += xv * w4.w;
            }
        }
    }
#pragma unroll
    for (int rr = 0; rr < R; rr++) {
        int r = rowBase + ty + rr * TY;
        float4 o;
        o.x = acc[rr][0] + bs[tx*4+0];
        o.y = acc[rr][1] + bs[tx*4+1];
        o.z = acc[rr][2] + bs[tx*4+2];
        o.w = acc[rr][3] + bs[tx*4+3];
        if (act == 1) {          /* leaky relu 0.1 */
            o.x = o.x > 0.f ? o.x : 0.1f*o.x; o.y = o.y > 0.f ? o.y : 0.1f*o.y;
            o.z = o.z > 0.f ? o.z : 0.1f*o.z; o.w = o.w > 0.f ? o.w : 0.1f*o.w;
        } else if (act == 2) {   /* relu */
            o.x = fmaxf(o.x,0.f); o.y = fmaxf(o.y,0.f);
            o.z = fmaxf(o.z,0.f); o.w = fmaxf(o.w,0.f);
        }
        *(float4*)(Y + r * NCOL + tx * 4) = o;
    }
}

/* ---------------- Wdiff = W[0:64] - W[64:128] ---------------------------- */
__global__ void wdiff_kernel(const float* __restrict__ Wc, float* __restrict__ Wd) {
    int i = blockIdx.x * blockDim.x + threadIdx.x;
    if (i < DD*DD) Wd[i] = Wc[i] - Wc[DD*DD + i];
}

/* ---------------- row sum of squares ------------------------------------- */
__global__ void sq_kernel(const float* __restrict__ ge, float* __restrict__ sq) {
    int r = blockIdx.x * blockDim.x + threadIdx.x;
    if (r >= NN) return;
    const float4* p = (const float4*)(ge + r * DD);
    float s0=0.f,s1=0.f,s2=0.f,s3=0.f;
#pragma unroll
    for (int d4 = 0; d4 < 16; d4++) {
        float4 v = p[d4];
        s0 += v.x*v.x; s1 += v.y*v.y; s2 += v.z*v.z; s3 += v.w*v.w;
    }
    sq[r] = (s0+s1)+(s2+s3);
}

/* ---------------- KNN pass 1: per-split partial top-5 --------------------
   Block: 32 queries x 512 points (split of 8). 256 threads.
   Thread tile: 4 queries x 4 points (16 accumulators).
   Q rows owned interleaved (qg + 8*qi), P rows (warpbase+pg + 4*pi) for
   conflict-free float4 LDS with row stride 76 floats.
   cp.async double-buffered point tiles of 128.                            */
__global__ __launch_bounds__(256, 2) void knn2_kernel(
    const float* __restrict__ ge, const float* __restrict__ sqg,
    float* __restrict__ pv, int* __restrict__ pig)
{
    extern __shared__ float sm[];
    float* Qs   = sm;                    /* 32*76  = 2432 */
    float* Ps   = sm + 2432;             /* 2*128*76 = 19456 */
    float* sqqs = sm + 2432 + 19456;     /* 32 */
    float* sqps = sqqs + 32;             /* 2*128 */

    const int tid  = threadIdx.x;
    const int lane = tid & 31, warp = tid >> 5;
    const int qg   = lane & 7;
    const int pg   = lane >> 3;          /* 0..3 */
    const int qbse = blockIdx.x * QT;
    const int split= blockIdx.y;
    const int bb   = blockIdx.z;
    const int pbase0 = split * PRANGE;
    const float* gb  = ge + bb * NPTS * DD;
    const float* sqb = sqg + bb * NPTS;
    const int wrow = warp * 16 + pg;

    /* stage Q (32x64 floats) */
    for (int f = tid; f < QT * 16; f += 256) {
        int r = f >> 4, c = f & 15;
        *(float4*)(Qs + r * 76 + c * 4) = *(const float4*)(gb + (qbse + r) * DD + c * 4);
    }
    if (tid < 32) sqqs[tid] = sqb[qbse + tid];

    /* prologue: fill tile 0 */
    {
        for (int f = tid; f < PT * 16; f += 256) {
            int r = f >> 4, c = f & 15;
            cp_async16(Ps + r * 76 + c * 4, gb + (pbase0 + r) * DD + c * 4);
        }
        if (tid < 32) cp_async16(sqps + tid * 4, sqb + pbase0 + tid * 4);
        cp_commit();
    }

    float acc[4][4];
    float tv[4][5]; int ti[4][5];
#pragma unroll
    for (int qi = 0; qi < 4; qi++) {
#pragma unroll
        for (int pi = 0; pi < 4; pi++) acc[qi][pi] = 0.f;
#pragma unroll
        for (int k = 0; k < 5; k++) { tv[qi][k] = FLT_MAX; ti[qi][k] = 0x7FFFFFFF; }
    }

    for (int t = 0; t < PRANGE / PT; t++) {
        if (t + 1 < PRANGE / PT) {
            __syncthreads();   /* prev compute done: buffer (t+1)&1 free */
            const int pb = pbase0 + (t + 1) * PT;
            float* Pd = Ps + ((t + 1) & 1) * 9728;
            for (int f = tid; f < PT * 16; f += 256) {
                int r = f >> 4, c = f & 15;
                cp_async16(Pd + r * 76 + c * 4, gb + (pb + r) * DD + c * 4);
            }
            if (tid < 32) cp_async16(sqps + ((t + 1) & 1) * 128 + tid * 4, sqb + pb + tid * 4);
            cp_commit();
            cp_wait<1>();
        } else {
            cp_wait<0>();
        }
        __syncthreads();

        const float* P  = Ps + (t & 1) * 9728;
        const float* SQ = sqps + (t & 1) * 128;

#pragma unroll 4
        for (int d4 = 0; d4 < 16; d4++) {
            float4 qv[4], pp[4];
#pragma unroll
            for (int qi = 0; qi < 4; qi++)
                qv[qi] = *(const float4*)(Qs + (qg + 8 * qi) * 76 + d4 * 4);
#pragma unroll
            for (int pi = 0; pi < 4; pi++)
                pp[pi] = *(const float4*)(P + (wrow + 4 * pi) * 76 + d4 * 4);
#pragma unroll
            for (int qi = 0; qi < 4; qi++) {
#pragma unroll
                for (int pi = 0; pi < 4; pi++) {
                    float a = acc[qi][pi];
                    a = fmaf(qv[qi].x, pp[pi].x, a);
                    a = fmaf(qv[qi].y, pp[pi].y, a);
                    a = fmaf(qv[qi].z, pp[pi].z, a);
                    a = fmaf(qv[qi].w, pp[pi].w, a);
                    acc[qi][pi] = a;
                }
            }
        }

        /* epilogue: distances + top-5 insertion (strict <, increasing idx) */
        const int pidx0 = pbase0 + t * PT + wrow;
#pragma unroll
        for (int qi = 0; qi < 4; qi++) {
            float sqj = sqqs[qg + 8 * qi];
#pragma unroll
            for (int pi = 0; pi < 4; pi++) {
                float dist = fmaxf(fmaf(-2.f, acc[qi][pi], sqj + SQ[wrow + 4 * pi]), 0.f);
                int   idx  = pidx0 + 4 * pi;
                acc[qi][pi] = 0.f;
                if (dist < tv[qi][4]) {
                    tv[qi][4] = dist; ti[qi][4] = idx;
#pragma unroll
                    for (int s2 = 4; s2 > 0; s2--) {
                        if (tv[qi][s2] < tv[qi][s2-1]) {
                            float fv = tv[qi][s2]; tv[qi][s2] = tv[qi][s2-1]; tv[qi][s2-1] = fv;
                            int  iv = ti[qi][s2]; ti[qi][s2] = ti[qi][s2-1]; ti[qi][s2-1] = iv;
                        }
                    }
                }
            }
        }
    }

    /* block merge: overlay shared; cand row stride 165 (odd*5 -> conflict-free) */
    __syncthreads();
    float* cv = sm;
    int*   ci = (int*)(sm + QT * 165);
#pragma unroll
    for (int qi = 0; qi < 4; qi++) {
        int q = qg + 8 * qi;
        int base = q * 165 + (warp * 4 + pg) * 5;
#pragma unroll
        for (int k = 0; k < 5; k++) { cv[base + k] = tv[qi][k]; ci[base + k] = ti[qi][k]; }
    }
    __syncthreads();
    if (tid < 32) {
        float bv[5]; int bi[5];
#pragma unroll
        for (int k = 0; k < 5; k++) { bv[k] = FLT_MAX; bi[k] = 0x7FFFFFFF; }
        for (int e = 0; e < 160; e++) {
            float v = cv[tid * 165 + e];
            int   i = ci[tid * 165 + e];
            if (v < bv[4] || (v == bv[4] && i < bi[4])) {
                bv[4] = v; bi[4] = i;
#pragma unroll
                for (int s2 = 4; s2 > 0; s2--) {
                    if (bv[s2] < bv[s2-1] || (bv[s2] == bv[s2-1] && bi[s2] < bi[s2-1])) {
                        float fv = bv[s2]; bv[s2] = bv[s2-1]; bv[s2-1] = fv;
                        int  iv = bi[s2]; bi[s2] = bi[s2-1]; bi[s2-1] = iv;
                    }
                }
            }
        }
        int qglob = qbse + tid;
        int base = ((bb * NPTS + qglob) * SPLITS + split) * 5;
#pragma unroll
        for (int k = 0; k < 5; k++) { pv[base + k] = bv[k]; pig[base + k] = bi[k]; }
    }
}

/* ---------------- KNN pass 2: merge splits -> idxflat -------------------- */
__global__ void knn_merge_kernel(const float* __restrict__ pv, const int* __restrict__ pig,
                                 int* __restrict__ idxflat)
{
    int gid = blockIdx.x * blockDim.x + threadIdx.x;
    if (gid >= NB * NPTS) return;
    int bb = gid >> 12;
    int q  = gid & (NPTS - 1);
    float bv[5]; int bi[5];
#pragma unroll
    for (int k = 0; k < 5; k++) { bv[k] = FLT_MAX; bi[k] = 0x7FFFFFFF; }
    for (int e = 0; e < SPLITS * 5; e++) {
        float v = pv[gid * (SPLITS * 5) + e];
        int   i = pig[gid * (SPLITS * 5) + e];
        if (v < bv[4] || (v == bv[4] && i < bi[4])) {
            bv[4] = v; bi[4] = i;
#pragma unroll
            for (int s2 = 4; s2 > 0; s2--) {
                if (bv[s2] < bv[s2-1] || (bv[s2] == bv[s2-1] && bi[s2] < bi[s2-1])) {
                    float fv = bv[s2]; bv[s2] = bv[s2-1]; bv[s2-1] = fv;
                    int  iv = bi[s2]; bi[s2] = bi[s2-1]; bi[s2-1] = iv;
                }
            }
        }
    }
#pragma unroll
    for (int k = 0; k < 5; k++)
        idxflat[bb * NKB + k * NPTS + q] = bi[k];
}

/* ---------------- logprobs: lp[b,i,kk,layer] ----------------------------- */
__global__ void lp_kernel(const float* __restrict__ ge, const int* __restrict__ idxflat,
                          const float* __restrict__ tptr, float* __restrict__ outp, int layer)
{
    int gid = blockIdx.x * blockDim.x + threadIdx.x;
    if (gid >= NB * NKB) return;
    int bb = gid / NKB;
    int m  = gid - bb * NKB;
    float tval = fminf(fmaxf(tptr[0], -5.0f), 5.0f);
    float t = expf(tval);
    int nb  = idxflat[bb * NKB + m];
    int ctr = m / KK;
    int kk  = m - ctr * KK;
    const float4* pa = (const float4*)(ge + (bb * NPTS + nb) * DD);
    const float4* pb = (const float4*)(ge + (bb * NPTS + ctr) * DD);
    float s = 0.f;
#pragma unroll
    for (int d4 = 0; d4 < 16; d4++) {
        float4 a = pa[d4], b4 = pb[d4];
        float dx=a.x-b4.x, dy=a.y-b4.y, dz=a.z-b4.z, dw=a.w-b4.w;
        s += dx*dx + dy*dy + dz*dz + dw*dw;
    }
    outp[((bb * NPTS + ctr) * KK + kk) * 2 + layer] = -s * t;
}

/* ---------------- scatter-max edge conv --------------------------------- */
__global__ void init_acc_kernel(unsigned* __restrict__ acc) {
    int i = blockIdx.x * blockDim.x + threadIdx.x;
    if (i < NN * DD) acc[i] = NEG_MAX_KEY;
}

__global__ void scatter_kernel(const int* __restrict__ idxflat,
                               const float* __restrict__ A, const float* __restrict__ B,
                               unsigned* __restrict__ acc)
{
    int gid = blockIdx.x * blockDim.x + threadIdx.x;
    if (gid >= EDGES * 16) return;
    int q  = gid >> 4;
    int cg = gid & 15;
    int mq = q >> 2;
    int bb = (q >> 1) & 1;
    int c  = q & 1;
    int m_s = mq;
    int m_d = mq + NKB / 2;
    int srcv = (c == 0) ? idxflat[bb * NKB + m_s] : (m_s / KK);
    int dstv = (c == 0) ? idxflat[bb * NKB + m_d] : (m_d / KK);
    srcv += bb * NPTS;
    dstv += bb * NPTS;
    float4 av = ((const float4*)A)[dstv * 16 + cg];
    float4 bv = ((const float4*)B)[srcv * 16 + cg];
    unsigned* base = acc + dstv * DD + cg * 4;
    atomicMax(base + 0, fkey(av.x + bv.x));
    atomicMax(base + 1, fkey(av.y + bv.y));
    atomicMax(base + 2, fkey(av.z + bv.z));
    atomicMax(base + 3, fkey(av.w + bv.w));
}

__global__ void decode_relu_kernel(const unsigned* __restrict__ acc, float* __restrict__ y) {
    int i = blockIdx.x * blockDim.x + threadIdx.x;
    if (i < NN * DD) y[i] = fmaxf(fdec(acc[i]), 0.0f);
}

/* ---------------- fused head: lrelu(x@Wf1+b)@Wf2+b ----------------------- */
__global__ __launch_bounds__(128) void head_kernel(
    const float* __restrict__ x3,
    const float* __restrict__ Wf1, const float* __restrict__ bf1,
    const float* __restrict__ Wf2, const float* __restrict__ bf2,
    float* __restrict__ out)
{
    __shared__ float w1[64 * 32];
    __shared__ float w2[32 * 8];
    __shared__ float b1s[32], b2s[8];
    int t = threadIdx.x;
    for (int f = t; f < 2048; f += 128) w1[f] = Wf1[f];
    for (int f = t; f < 256;  f += 128) w2[f] = Wf2[f];
    if (t < 32) b1s[t] = bf1[t];
    if (t < 8)  b2s[t] = bf2[t];
    __syncthreads();
    int r = blockIdx.x * 128 + t;
    if (r >= NN) return;
    float xr[64];
#pragma unroll
    for (int d4 = 0; d4 < 16; d4++) {
        float4 v = ((const float4*)(x3 + r * DD))[d4];
        xr[d4*4+0]=v.x; xr[d4*4+1]=v.y; xr[d4*4+2]=v.z; xr[d4*4+3]=v.w;
    }
    float o[8];
#pragma unroll
    for (int k = 0; k < 8; k++) o[k] = b2s[k];
    for (int jj = 0; jj < 32; jj++) {
        float h0=0.f,h1=0.f,h2=0.f,h3=0.f;
#pragma unroll
        for (int k = 0; k < 64; k += 4) {
            h0 += xr[k+0] * w1[(k+0)*32 + jj];
            h1 += xr[k+1] * w1[(k+1)*32 + jj];
            h2 += xr[k+2] * w1[(k+2)*32 + jj];
            h3 += xr[k+3] * w1[(k+3)*32 + jj];
        }
        float h = ((h0+h1)+(h2+h3)) + b1s[jj];
        h = h > 0.f ? h : 0.1f * h;
#pragma unroll
        for (int k = 0; k < 8; k++) o[k] += h * w2[jj*8 + k];
    }
#pragma unroll
    for (int k = 0; k < 8; k++) out[r * 8 + k] = o[k];
}

/* ---------------- launch ------------------------------------------------- */
#define KNN_SMEM 88704

extern "C" void kernel_launch(void* const* d_in, const int* in_sizes, int n_in,
                              void* d_out, int out_size)
{
    const float* x     = (const float*)d_in[0];
    const float* W_pre = (const float*)d_in[1];
    const float* b_pre = (const float*)d_in[2];
    const float* W_d1  = (const float*)d_in[3];
    const float* b_d1  = (const float*)d_in[4];
    const float* t1    = (const float*)d_in[5];
    const float* W_c1  = (const float*)d_in[6];
    const float* b_c1  = (const float*)d_in[7];
    const float* W_d2  = (const float*)d_in[8];
    const float* b_d2  = (const float*)d_in[9];
    const float* t2    = (const float*)d_in[10];
    const float* W_c2  = (const float*)d_in[11];
    const float* b_c2  = (const float*)d_in[12];
    const float* W_f1  = (const float*)d_in[13];
    const float* b_f1  = (const float*)d_in[14];
    const float* W_f2  = (const float*)d_in[15];
    const float* b_f2  = (const float*)d_in[16];

    float* out = (float*)d_out;            /* [2,4096,8] = 65536 floats   */
    float* lp  = out + NN * 8;             /* [2,4096,5,2] = 81920 floats */

    float *p_xf1, *p_ge1, *p_ge2, *p_sq, *p_A, *p_B, *p_x2, *p_x3, *p_Wdiff, *p_pv;
    int *p_idx1, *p_idx2, *p_pi;
    unsigned *p_acc;
    cudaGetSymbolAddress((void**)&p_xf1,  g_xf1);
    cudaGetSymbolAddress((void**)&p_ge1,  g_ge1);
    cudaGetSymbolAddress((void**)&p_ge2,  g_ge2);
    cudaGetSymbolAddress((void**)&p_sq,   g_sq);
    cudaGetSymbolAddress((void**)&p_idx1, g_idx1);
    cudaGetSymbolAddress((void**)&p_idx2, g_idx2);
    cudaGetSymbolAddress((void**)&p_A,    g_A);
    cudaGetSymbolAddress((void**)&p_B,    g_B);
    cudaGetSymbolAddress((void**)&p_acc,  g_acc);
    cudaGetSymbolAddress((void**)&p_x2,   g_x2);
    cudaGetSymbolAddress((void**)&p_x3,   g_x3);
    cudaGetSymbolAddress((void**)&p_Wdiff,g_Wdiff);
    cudaGetSymbolAddress((void**)&p_pv,   g_pv);
    cudaGetSymbolAddress((void**)&p_pi,   g_pi);

    cudaFuncSetAttribute(knn2_kernel, cudaFuncAttributeMaxDynamicSharedMemorySize, KNN_SMEM);

    const float* nul = nullptr;
    dim3 knn_grid(NPTS/QT, SPLITS, NB);

    /* pre MLP + embed 1 */
    gemm_act<64><<<NN/64, 256>>>(x,     32, nul, 0, W_pre, b_pre, p_xf1, 1);
    gemm_act<64><<<NN/64, 256>>>(p_xf1, 64, nul, 0, W_d1,  b_d1,  p_ge1, 0);

    /* knn 1 + lp 1 */
    sq_kernel<<<NN/256, 256>>>(p_ge1, p_sq);
    knn2_kernel<<<knn_grid, 256, KNN_SMEM>>>(p_ge1, p_sq, p_pv, p_pi);
    knn_merge_kernel<<<(NB*NPTS)/256, 256>>>(p_pv, p_pi, p_idx1);
    lp_kernel<<<(NB*NKB)/256, 256>>>(p_ge1, p_idx1, t1, lp, 0);

    /* edge conv 1 */
    wdiff_kernel<<<(DD*DD)/256, 256>>>(W_c1, p_Wdiff);
    gemm_act<64><<<NN/64, 256>>>(p_xf1, 64, nul, 0, p_Wdiff,      b_c1, p_A, 0);
    gemm_act<64><<<NN/64, 256>>>(p_xf1, 64, nul, 0, W_c1 + DD*DD, nul,  p_B, 0);
    init_acc_kernel<<<(NN*DD)/256, 256>>>(p_acc);
    scatter_kernel<<<(EDGES*16)/256, 256>>>(p_idx1, p_A, p_B, p_acc);
    decode_relu_kernel<<<(NN*DD)/256, 256>>>(p_acc, p_x2);

    /* embed 2 on concat[ge1, x2] */
    gemm_act<64><<<NN/64, 256>>>(p_ge1, 64, p_x2, 64, W_d2, b_d2, p_ge2, 0);

    /* knn 2 + lp 2 */
    sq_kernel<<<NN/256, 256>>>(p_ge2, p_sq);
    knn2_kernel<<<knn_grid, 256, KNN_SMEM>>>(p_ge2, p_sq, p_pv, p_pi);
    knn_merge_kernel<<<(NB*NPTS)/256, 256>>>(p_pv, p_pi, p_idx2);
    lp_kernel<<<(NB*NKB)/256, 256>>>(p_ge2, p_idx2, t2, lp, 1);

    /* edge conv 2 */
    wdiff_kernel<<<(DD*DD)/256, 256>>>(W_c2, p_Wdiff);
    gemm_act<64><<<NN/64, 256>>>(p_x2, 64, nul, 0, p_Wdiff,      b_c2, p_A, 0);
    gemm_act<64><<<NN/64, 256>>>(p_x2, 64, nul, 0, W_c2 + DD*DD, nul,  p_B, 0);
    init_acc_kernel<<<(NN*DD)/256, 256>>>(p_acc);
    scatter_kernel<<<(EDGES*16)/256, 256>>>(p_idx2, p_A, p_B, p_acc);
    decode_relu_kernel<<<(NN*DD)/256, 256>>>(p_acc, p_x3);

    /* head */
    head_kernel<<<NN/128, 128>>>(p_x3, W_f1, b_f1, W_f2, b_f2, out);
}

// round 3
// speedup vs baseline: 1.3928x; 1.3928x over previous
#include <cuda_runtime.h>
#include <float.h>
#include <math.h>

#define NPTS 4096
#define NB 2
#define NN 8192
#define DD 64
#define KK 5
#define NKB (NPTS*KK)      /* 20480 flat (k-major) per batch */
#define EDGES (NB*NKB)     /* 40960 edges */

/* ---------------- scratch (device globals; no allocation allowed) -------- */
__device__ float    g_xf1[NN*DD];
__device__ float    g_ge1[NN*DD];
__device__ float    g_ge2[NN*DD];
__device__ float    g_sq [NN];
__device__ int      g_idx1[NB*NKB];
__device__ int      g_idx2[NB*NKB];
__device__ float    g_A  [NN*DD];
__device__ float    g_B  [NN*DD];
__device__ unsigned g_acc[NN*DD];
__device__ float    g_x2 [NN*DD];
__device__ float    g_x3 [NN*DD];

/* ordered float<->uint key (monotone map, finite floats) */
__device__ __forceinline__ unsigned fkey(float f) {
    unsigned u = __float_as_uint(f);
    return u ^ ((unsigned)(((int)u) >> 31) | 0x80000000u);
}
__device__ __forceinline__ float fdec(unsigned u) {
    unsigned v = u ^ ((u & 0x80000000u) ? 0x80000000u : 0xFFFFFFFFu);
    return __uint_as_float(v);
}
#define NEG_MAX_KEY 0x00800000u   /* fkey(-FLT_MAX) */

/* cp.async helpers */
__device__ __forceinline__ void cp_async16(void* smem_dst, const void* gsrc) {
    unsigned s = (unsigned)__cvta_generic_to_shared(smem_dst);
    asm volatile("cp.async.ca.shared.global [%0], [%1], 16;" :: "r"(s), "l"(gsrc));
}
__device__ __forceinline__ void cp_commit() {
    asm volatile("cp.async.commit_group;" ::: "memory");
}
template<int N> __device__ __forceinline__ void cp_wait() {
    asm volatile("cp.async.wait_group %0;" :: "n"(N) : "memory");
}

/* ---------------- generic small GEMM: Y = act(X@W + b), 64 rows/block ---- */
template<int NCOL>
__global__ __launch_bounds__(256) void gemm_act(
    const float* __restrict__ X1, int k1,
    const float* __restrict__ X2, int k2,
    const float* __restrict__ W, const float* __restrict__ bias,
    float* __restrict__ Y, int act)
{
    constexpr int G  = NCOL / 4;
    constexpr int TY = 256 / G;
    constexpr int R  = 64 / TY;
    __shared__ float Ws[128 * NCOL];
    __shared__ float Xs[64 * 33];
    __shared__ float bs[NCOL];
    const int t = threadIdx.x;
    const int rowBase = blockIdx.x * 64;
    const int KD = k1 + k2;

    for (int f = t; f < KD * NCOL; f += 256) Ws[f] = W[f];
    if (t < NCOL) bs[t] = (bias != nullptr) ? bias[t] : 0.0f;

    const int tx = t % G, ty = t / G;
    float acc[R][4];
#pragma unroll
    for (int rr = 0; rr < R; rr++) { acc[rr][0]=0.f; acc[rr][1]=0.f; acc[rr][2]=0.f; acc[rr][3]=0.f; }

    for (int ko = 0; ko < KD; ko += 32) {
        const float* Xsrc; int stride, koff;
        if (ko < k1) { Xsrc = X1; stride = k1; koff = ko; }
        else         { Xsrc = X2; stride = k2; koff = ko - k1; }
        __syncthreads();
        for (int f = t; f < 64 * 32; f += 256) {
            int r = f >> 5, k = f & 31;
            Xs[r * 33 + k] = Xsrc[(rowBase + r) * stride + koff + k];
        }
        __syncthreads();
#pragma unroll
        for (int k = 0; k < 32; k++) {
            float4 w4 = *(const float4*)(Ws + (ko + k) * NCOL + tx * 4);
#pragma unroll
            for (int rr = 0; rr < R; rr++) {
                float xv = Xs[(ty + rr * TY) * 33 + k];
                acc[rr][0] += xv * w4.x; acc[rr][1] += xv * w4.y;
                acc[rr][2] += xv * w4.z; acc[rr][3] += xv * w4.w;
            }
        }
    }
#pragma unroll
    for (int rr = 0; rr < R; rr++) {
        int r = rowBase + ty + rr * TY;
        float4 o;
        o.x = acc[rr][0] + bs[tx*4+0];
        o.y = acc[rr][1] + bs[tx*4+1];
        o.z = acc[rr][2] + bs[tx*4+2];
        o.w = acc[rr][3] + bs[tx*4+3];
        if (act == 1) {          /* leaky relu 0.1 */
            o.x = o.x > 0.f ? o.x : 0.1f*o.x; o.y = o.y > 0.f ? o.y : 0.1f*o.y;
            o.z = o.z > 0.f ? o.z : 0.1f*o.z; o.w = o.w > 0.f ? o.w : 0.1f*o.w;
        } else if (act == 2) {   /* relu */
            o.x = fmaxf(o.x,0.f); o.y = fmaxf(o.y,0.f);
            o.z = fmaxf(o.z,0.f); o.w = fmaxf(o.w,0.f);
        }
        *(float4*)(Y + r * NCOL + tx * 4) = o;
    }
}

/* -------- fused EdgeConv GEMMs: A = X@(Wtop-Wbot)+bias, B = X@Wbot ------- */
__global__ __launch_bounds__(256) void gemm_ab(
    const float* __restrict__ X, const float* __restrict__ Wc,
    const float* __restrict__ bias, float* __restrict__ A, float* __restrict__ B)
{
    __shared__ float Ws[128 * 64];
    __shared__ float Xs[64 * 33];
    __shared__ float bs[64];
    const int t = threadIdx.x;
    const int rowBase = blockIdx.x * 64;
    for (int f = t; f < 128 * 64; f += 256) Ws[f] = Wc[f];
    if (t < 64) bs[t] = bias[t];

    const int tx = t % 16, ty = t / 16;        /* 16 col-groups x 16 rows */
    float aT[4][4], aB[4][4];
#pragma unroll
    for (int rr = 0; rr < 4; rr++)
#pragma unroll
        for (int c = 0; c < 4; c++) { aT[rr][c] = 0.f; aB[rr][c] = 0.f; }

    for (int ko = 0; ko < 64; ko += 32) {
        __syncthreads();
        for (int f = t; f < 64 * 32; f += 256) {
            int r = f >> 5, k = f & 31;
            Xs[r * 33 + k] = X[(rowBase + r) * 64 + ko + k];
        }
        __syncthreads();
#pragma unroll
        for (int k = 0; k < 32; k++) {
            float4 wt = *(const float4*)(Ws + (ko + k) * 64 + tx * 4);
            float4 wb = *(const float4*)(Ws + (64 + ko + k) * 64 + tx * 4);
#pragma unroll
            for (int rr = 0; rr < 4; rr++) {
                float xv = Xs[(ty + rr * 16) * 33 + k];
                aT[rr][0] = fmaf(xv, wt.x, aT[rr][0]); aT[rr][1] = fmaf(xv, wt.y, aT[rr][1]);
                aT[rr][2] = fmaf(xv, wt.z, aT[rr][2]); aT[rr][3] = fmaf(xv, wt.w, aT[rr][3]);
                aB[rr][0] = fmaf(xv, wb.x, aB[rr][0]); aB[rr][1] = fmaf(xv, wb.y, aB[rr][1]);
                aB[rr][2] = fmaf(xv, wb.z, aB[rr][2]); aB[rr][3] = fmaf(xv, wb.w, aB[rr][3]);
            }
        }
    }
#pragma unroll
    for (int rr = 0; rr < 4; rr++) {
        int r = rowBase + ty + rr * 16;
        float4 ao, bo;
        ao.x = aT[rr][0] - aB[rr][0] + bs[tx*4+0];
        ao.y = aT[rr][1] - aB[rr][1] + bs[tx*4+1];
        ao.z = aT[rr][2] - aB[rr][2] + bs[tx*4+2];
        ao.w = aT[rr][3] - aB[rr][3] + bs[tx*4+3];
        bo.x = aB[rr][0]; bo.y = aB[rr][1]; bo.z = aB[rr][2]; bo.w = aB[rr][3];
        *(float4*)(A + r * 64 + tx * 4) = ao;
        *(float4*)(B + r * 64 + tx * 4) = bo;
    }
}

/* ---------------- row sum of squares ------------------------------------- */
__global__ void sq_kernel(const float* __restrict__ ge, float* __restrict__ sq) {
    int r = blockIdx.x * blockDim.x + threadIdx.x;
    if (r >= NN) return;
    const float4* p = (const float4*)(ge + r * DD);
    float s0=0.f,s1=0.f,s2=0.f,s3=0.f;
#pragma unroll
    for (int d4 = 0; d4 < 16; d4++) {
        float4 v = p[d4];
        s0 += v.x*v.x; s1 += v.y*v.y; s2 += v.z*v.z; s3 += v.w*v.w;
    }
    sq[r] = (s0+s1)+(s2+s3);
}

/* ---------------- KNN: 1 query per lane, broadcast points, cp.async ------
   Block: 32 queries (one per lane), 8 warps each own 8 point-rows per
   64-point tile (broadcast LDS). Query vector in 64 registers.
   Double-buffered tiles via cp.async. Single wave: 256 blocks, 2/SM.      */
__global__ __launch_bounds__(256, 2) void knn3_kernel(
    const float* __restrict__ ge, const float* __restrict__ sqg,
    int* __restrict__ idxflat)
{
    __shared__ float Ps[2][64 * 64];
    __shared__ float sqs[2][64];

    const int tid  = threadIdx.x;
    const int lane = tid & 31, warp = tid >> 5;
    const int qbase = blockIdx.x * 32;
    const int bb    = blockIdx.y;
    const float* gb  = ge + bb * NPTS * DD;
    const float* sqb = sqg + bb * NPTS;

    float qv[DD];
#pragma unroll
    for (int d4 = 0; d4 < 16; d4++) {
        float4 v = ((const float4*)(gb + (qbase + lane) * DD))[d4];
        qv[4*d4+0]=v.x; qv[4*d4+1]=v.y; qv[4*d4+2]=v.z; qv[4*d4+3]=v.w;
    }
    const float sqj = sqb[qbase + lane];

    float tv[5]; int ti[5];
#pragma unroll
    for (int k = 0; k < 5; k++) { tv[k] = FLT_MAX; ti[k] = 0x7FFFFFFF; }

    /* prologue: tile 0 */
    for (int f = tid; f < 1024; f += 256)
        cp_async16(&Ps[0][(f >> 4) * 64 + (f & 15) * 4],
                   gb + (f >> 4) * DD + (f & 15) * 4);
    if (tid < 16) cp_async16(&sqs[0][tid * 4], sqb + tid * 4);
    cp_commit();

    for (int tt = 0; tt < 64; tt++) {
        if (tt < 63) {
            __syncthreads();            /* compute on buf[(tt+1)&1] finished */
            const float* src = gb + (tt + 1) * 64 * DD;
            float* dst = Ps[(tt + 1) & 1];
            for (int f = tid; f < 1024; f += 256)
                cp_async16(dst + (f >> 4) * 64 + (f & 15) * 4,
                           src + (f >> 4) * DD + (f & 15) * 4);
            if (tid < 16) cp_async16(&sqs[(tt + 1) & 1][tid * 4],
                                     sqb + (tt + 1) * 64 + tid * 4);
            cp_commit();
            cp_wait<1>();               /* tile tt landed */
        } else {
            cp_wait<0>();
        }
        __syncthreads();

        const float* P  = Ps[tt & 1];
        const float* SQ = sqs[tt & 1];
#pragma unroll
        for (int p = 0; p < 8; p++) {
            const int row = warp * 8 + p;
            const float4* pr = (const float4*)(P + row * 64);
            float4 v0 = pr[0];
            float a0 = qv[0]*v0.x, a1 = qv[1]*v0.y, a2 = qv[2]*v0.z, a3 = qv[3]*v0.w;
#pragma unroll
            for (int d4 = 1; d4 < 16; d4++) {
                float4 v = pr[d4];
                a0 = fmaf(qv[4*d4+0], v.x, a0);
                a1 = fmaf(qv[4*d4+1], v.y, a1);
                a2 = fmaf(qv[4*d4+2], v.z, a2);
                a3 = fmaf(qv[4*d4+3], v.w, a3);
            }
            float dot  = (a0 + a1) + (a2 + a3);
            float dist = fmaxf(fmaf(-2.0f, dot, sqj + SQ[row]), 0.0f);
            int   idx  = tt * 64 + row;
            if (dist < tv[4]) {
                tv[4] = dist; ti[4] = idx;
#pragma unroll
                for (int s2 = 4; s2 > 0; s2--) {
                    if (tv[s2] < tv[s2-1]) {
                        float fv = tv[s2]; tv[s2] = tv[s2-1]; tv[s2-1] = fv;
                        int  iv = ti[s2]; ti[s2] = ti[s2-1]; ti[s2-1] = iv;
                    }
                }
            }
        }
    }

    /* block merge: 8 warps x 5 candidates per query (lane). stride 41. */
    __syncthreads();
    float* cv = Ps[0];
    int*   ci = (int*)(Ps[0] + 32 * 41);
#pragma unroll
    for (int k = 0; k < 5; k++) {
        cv[lane * 41 + warp * 5 + k] = tv[k];
        ci[lane * 41 + warp * 5 + k] = ti[k];
    }
    __syncthreads();
    if (warp == 0) {
        float bv[5]; int bi[5];
#pragma unroll
        for (int k = 0; k < 5; k++) { bv[k] = FLT_MAX; bi[k] = 0x7FFFFFFF; }
        for (int e = 0; e < 40; e++) {
            float v = cv[lane * 41 + e];
            int   i = ci[lane * 41 + e];
            if (v < bv[4] || (v == bv[4] && i < bi[4])) {
                bv[4] = v; bi[4] = i;
#pragma unroll
                for (int s2 = 4; s2 > 0; s2--) {
                    if (bv[s2] < bv[s2-1] || (bv[s2] == bv[s2-1] && bi[s2] < bi[s2-1])) {
                        float fv = bv[s2]; bv[s2] = bv[s2-1]; bv[s2-1] = fv;
                        int  iv = bi[s2]; bi[s2] = bi[s2-1]; bi[s2-1] = iv;
                    }
                }
            }
        }
#pragma unroll
        for (int k = 0; k < 5; k++)
            idxflat[bb * NKB + k * NPTS + qbase + lane] = bi[k];
    }
}

/* ---------------- logprobs: lp[b,i,kk,layer] ----------------------------- */
__global__ void lp_kernel(const float* __restrict__ ge, const int* __restrict__ idxflat,
                          const float* __restrict__ tptr, float* __restrict__ outp, int layer)
{
    int gid = blockIdx.x * blockDim.x + threadIdx.x;
    if (gid >= NB * NKB) return;
    int bb = gid / NKB;
    int m  = gid - bb * NKB;
    float tval = fminf(fmaxf(tptr[0], -5.0f), 5.0f);
    float t = expf(tval);
    int nb  = idxflat[bb * NKB + m];
    int ctr = m / KK;
    int kk  = m - ctr * KK;
    const float4* pa = (const float4*)(ge + (bb * NPTS + nb) * DD);
    const float4* pb = (const float4*)(ge + (bb * NPTS + ctr) * DD);
    float s = 0.f;
#pragma unroll
    for (int d4 = 0; d4 < 16; d4++) {
        float4 a = pa[d4], b4 = pb[d4];
        float dx=a.x-b4.x, dy=a.y-b4.y, dz=a.z-b4.z, dw=a.w-b4.w;
        s += dx*dx + dy*dy + dz*dz + dw*dw;
    }
    outp[((bb * NPTS + ctr) * KK + kk) * 2 + layer] = -s * t;
}

/* ---------------- scatter-max edge conv --------------------------------- */
__global__ void init_acc_kernel(unsigned* __restrict__ acc) {
    int i = blockIdx.x * blockDim.x + threadIdx.x;
    if (i < NN * DD) acc[i] = NEG_MAX_KEY;
}

__global__ void scatter_kernel(const int* __restrict__ idxflat,
                               const float* __restrict__ A, const float* __restrict__ B,
                               unsigned* __restrict__ acc)
{
    int gid = blockIdx.x * blockDim.x + threadIdx.x;
    if (gid >= EDGES * 16) return;
    int q  = gid >> 4;
    int cg = gid & 15;
    int mq = q >> 2;
    int bb = (q >> 1) & 1;
    int c  = q & 1;
    int m_s = mq;
    int m_d = mq + NKB / 2;
    int srcv = (c == 0) ? idxflat[bb * NKB + m_s] : (m_s / KK);
    int dstv = (c == 0) ? idxflat[bb * NKB + m_d] : (m_d / KK);
    srcv += bb * NPTS;
    dstv += bb * NPTS;
    float4 av = ((const float4*)A)[dstv * 16 + cg];
    float4 bv = ((const float4*)B)[srcv * 16 + cg];
    unsigned* base = acc + dstv * DD + cg * 4;
    atomicMax(base + 0, fkey(av.x + bv.x));
    atomicMax(base + 1, fkey(av.y + bv.y));
    atomicMax(base + 2, fkey(av.z + bv.z));
    atomicMax(base + 3, fkey(av.w + bv.w));
}

__global__ void decode_relu_kernel(const unsigned* __restrict__ acc, float* __restrict__ y) {
    int i = blockIdx.x * blockDim.x + threadIdx.x;
    if (i < NN * DD) y[i] = fmaxf(fdec(acc[i]), 0.0f);
}

/* ---------------- fused head: lrelu(x@Wf1+b)@Wf2+b ----------------------- */
__global__ __launch_bounds__(128) void head_kernel(
    const float* __restrict__ x3,
    const float* __restrict__ Wf1, const float* __restrict__ bf1,
    const float* __restrict__ Wf2, const float* __restrict__ bf2,
    float* __restrict__ out)
{
    __shared__ float w1[64 * 32];
    __shared__ float w2[32 * 8];
    __shared__ float b1s[32], b2s[8];
    int t = threadIdx.x;
    for (int f = t; f < 2048; f += 128) w1[f] = Wf1[f];
    for (int f = t; f < 256;  f += 128) w2[f] = Wf2[f];
    if (t < 32) b1s[t] = bf1[t];
    if (t < 8)  b2s[t] = bf2[t];
    __syncthreads();
    int r = blockIdx.x * 128 + t;
    if (r >= NN) return;
    float xr[64];
#pragma unroll
    for (int d4 = 0; d4 < 16; d4++) {
        float4 v = ((const float4*)(x3 + r * DD))[d4];
        xr[d4*4+0]=v.x; xr[d4*4+1]=v.y; xr[d4*4+2]=v.z; xr[d4*4+3]=v.w;
    }
    float o[8];
#pragma unroll
    for (int k = 0; k < 8; k++) o[k] = b2s[k];
    for (int jj = 0; jj < 32; jj++) {
        float h0=0.f,h1=0.f,h2=0.f,h3=0.f;
#pragma unroll
        for (int k = 0; k < 64; k += 4) {
            h0 += xr[k+0] * w1[(k+0)*32 + jj];
            h1 += xr[k+1] * w1[(k+1)*32 + jj];
            h2 += xr[k+2] * w1[(k+2)*32 + jj];
            h3 += xr[k+3] * w1[(k+3)*32 + jj];
        }
        float h = ((h0+h1)+(h2+h3)) + b1s[jj];
        h = h > 0.f ? h : 0.1f * h;
#pragma unroll
        for (int k = 0; k < 8; k++) o[k] += h * w2[jj*8 + k];
    }
#pragma unroll
    for (int k = 0; k < 8; k++) out[r * 8 + k] = o[k];
}

/* ---------------- launch ------------------------------------------------- */
extern "C" void kernel_launch(void* const* d_in, const int* in_sizes, int n_in,
                              void* d_out, int out_size)
{
    const float* x     = (const float*)d_in[0];
    const float* W_pre = (const float*)d_in[1];
    const float* b_pre = (const float*)d_in[2];
    const float* W_d1  = (const float*)d_in[3];
    const float* b_d1  = (const float*)d_in[4];
    const float* t1    = (const float*)d_in[5];
    const float* W_c1  = (const float*)d_in[6];
    const float* b_c1  = (const float*)d_in[7];
    const float* W_d2  = (const float*)d_in[8];
    const float* b_d2  = (const float*)d_in[9];
    const float* t2    = (const float*)d_in[10];
    const float* W_c2  = (const float*)d_in[11];
    const float* b_c2  = (const float*)d_in[12];
    const float* W_f1  = (const float*)d_in[13];
    const float* b_f1  = (const float*)d_in[14];
    const float* W_f2  = (const float*)d_in[15];
    const float* b_f2  = (const float*)d_in[16];

    float* out = (float*)d_out;            /* [2,4096,8] = 65536 floats   */
    float* lp  = out + NN * 8;             /* [2,4096,5,2] = 81920 floats */

    float *p_xf1, *p_ge1, *p_ge2, *p_sq, *p_A, *p_B, *p_x2, *p_x3;
    int *p_idx1, *p_idx2;
    unsigned *p_acc;
    cudaGetSymbolAddress((void**)&p_xf1,  g_xf1);
    cudaGetSymbolAddress((void**)&p_ge1,  g_ge1);
    cudaGetSymbolAddress((void**)&p_ge2,  g_ge2);
    cudaGetSymbolAddress((void**)&p_sq,   g_sq);
    cudaGetSymbolAddress((void**)&p_idx1, g_idx1);
    cudaGetSymbolAddress((void**)&p_idx2, g_idx2);
    cudaGetSymbolAddress((void**)&p_A,    g_A);
    cudaGetSymbolAddress((void**)&p_B,    g_B);
    cudaGetSymbolAddress((void**)&p_acc,  g_acc);
    cudaGetSymbolAddress((void**)&p_x2,   g_x2);
    cudaGetSymbolAddress((void**)&p_x3,   g_x3);

    const float* nul = nullptr;
    dim3 knn_grid(NPTS / 32, NB);

    /* pre MLP + embed 1 */
    gemm_act<64><<<NN/64, 256>>>(x,     32, nul, 0, W_pre, b_pre, p_xf1, 1);
    gemm_act<64><<<NN/64, 256>>>(p_xf1, 64, nul, 0, W_d1,  b_d1,  p_ge1, 0);

    /* knn 1 + lp 1 */
    sq_kernel<<<NN/256, 256>>>(p_ge1, p_sq);
    knn3_kernel<<<knn_grid, 256>>>(p_ge1, p_sq, p_idx1);
    lp_kernel<<<(NB*NKB)/256, 256>>>(p_ge1, p_idx1, t1, lp, 0);

    /* edge conv 1 */
    gemm_ab<<<NN/64, 256>>>(p_xf1, W_c1, b_c1, p_A, p_B);
    init_acc_kernel<<<(NN*DD)/256, 256>>>(p_acc);
    scatter_kernel<<<(EDGES*16)/256, 256>>>(p_idx1, p_A, p_B, p_acc);
    decode_relu_kernel<<<(NN*DD)/256, 256>>>(p_acc, p_x2);

    /* embed 2 on concat[ge1, x2] */
    gemm_act<64><<<NN/64, 256>>>(p_ge1, 64, p_x2, 64, W_d2, b_d2, p_ge2, 0);

    /* knn 2 + lp 2 */
    sq_kernel<<<NN/256, 256>>>(p_ge2, p_sq);
    knn3_kernel<<<knn_grid, 256>>>(p_ge2, p_sq, p_idx2);
    lp_kernel<<<(NB*NKB)/256, 256>>>(p_ge2, p_idx2, t2, lp, 1);

    /* edge conv 2 */
    gemm_ab<<<NN/64, 256>>>(p_x2, W_c2, b_c2, p_A, p_B);
    init_acc_kernel<<<(NN*DD)/256, 256>>>(p_acc);
    scatter_kernel<<<(EDGES*16)/256, 256>>>(p_idx2, p_A, p_B, p_acc);
    decode_relu_kernel<<<(NN*DD)/256, 256>>>(p_acc, p_x3);

    /* head */
    head_kernel<<<NN/128, 128>>>(p_x3, W_f1, b_f1, W_f2, b_f2, out);
}